// round 11
// baseline (speedup 1.0000x reference)
#include <cuda_runtime.h>
#include <cuda_bf16.h>
#include <cstdint>

// ============================================================================
// RelationEmbeddingUpdater: out = where(type==1, emb @ W^T + b, emb)
//
// One CTA per PAIR of 128-row tiles (grid = ceil(N/256)). bf16 2-way-split
// GEMM (3 MMA passes ~ fp32 accuracy), fp32 accum in TMEM (two 256-col
// accumulators). Chunk-outer, tile-inner loop; W staged once per chunk.
//  - A staged via cp.async with DEPTH-2 prefetch (two 32KB groups in flight
//    per SM -> ~2x sustainable DRAM demand vs depth-1), 4 rotating buffers,
//    converted IN PLACE (regs across a barrier).
//  - W: single 64KB buffer; overwrite guarded by tid0-only commit(s-1) wait
//    (overlapped with the convert phase of the other 255 threads).
//  - relation-only fp32->bf16 split; entity rows passthrough from registers.
// ============================================================================

#define D_DIM 256
#define TILE_M 128

// ---------------- smem layout (dynamic) ----------------
#define SMEM_TMEM_PTR 0
#define MB_COMMIT     16           // 8 mbarriers x 8B (per-step MMA commits), single-use
#define MB_WFULL      80           // 4 mbarriers x 8B (W DMA completion), single-use
#define SMEM_BIAS     128          // 256 floats
#define SMEM_TMASK    1152         // 256 bytes (row types for both tiles)
#define SMEM_A        2048         // 4 bufs x 32KB (fp32 staging -> in-place bf16 hi|lo)
#define SMEM_W        133120       // 1 buf: hi 32KB + lo 32KB (1024-aligned)
#define SMEM_BYTES    198656

// idesc kind::f16: dtype=F32, atype=BF16, btype=BF16, N=256, M=128, cg1
#define MMA_IDESC 0x8400490u

// Pre-split + PRE-SWIZZLED W: chunk c occupies bytes [c*32768,(c+1)*32768);
// element (j,kk) at SW128(j*128 + kk*2). Linear bulk copy into 1024-aligned
// smem preserves the swizzle (SW128 permutes bits [6:4] within 1024B blocks).
__device__ __align__(128) __nv_bfloat16 g_Whi[D_DIM * D_DIM];
__device__ __align__(128) __nv_bfloat16 g_Wlo[D_DIM * D_DIM];

// node_type dtype flag: 1 if int64, 0 if int32
__device__ int g_is64;

#if defined(__CUDA_ARCH_FEAT_SM103_ALL) || defined(__CUDA_ARCH_FEAT_SM100_ALL) || defined(__CUDA_ARCH_FEAT_SM101_ALL)
#define HAS_TCGEN05 1
#else
#define HAS_TCGEN05 0
#endif

// ---------------- helpers ----------------
static __device__ __forceinline__ uint32_t smem_u32(const void* p) {
    uint32_t a;
    asm("{ .reg .u64 t; cvta.to.shared.u64 t, %1; cvt.u32.u64 %0, t; }"
        : "=r"(a) : "l"(p));
    return a;
}
static __device__ __forceinline__ uint32_t elect_one() {
    uint32_t p;
    asm volatile("{ .reg .pred p; elect.sync _|p, 0xFFFFFFFF; selp.b32 %0, 1, 0, p; }"
                 : "=r"(p));
    return p;
}
#define SW128(o) ((o) ^ (((o) >> 3) & 0x70))

static constexpr uint64_t SMEM_DESC_BASE_SW128 =
    (uint64_t(2) << 61) | (uint64_t(1) << 46) | (uint64_t(64) << 32) | (uint64_t(1) << 16);
#define MAKE_SMEM_DESC(base_addr) \
    (SMEM_DESC_BASE_SW128 | ((uint64_t)((base_addr) >> 4) & 0x3FFF))

#define TCGEN05_ALLOC(smem_addr, nCols) \
    asm volatile("tcgen05.alloc.cta_group::1.sync.aligned.shared::cta.b32 [%0], %1;" \
        :: "r"((uint32_t)(smem_addr)), "r"((uint32_t)(nCols)) : "memory")
#define TCGEN05_DEALLOC(tmem_addr, nCols) \
    asm volatile("tcgen05.dealloc.cta_group::1.sync.aligned.b32 %0, %1;" \
        :: "r"(tmem_addr), "r"((uint32_t)(nCols)))
#define TCGEN05_RELINQUISH() \
    asm volatile("tcgen05.relinquish_alloc_permit.cta_group::1.sync.aligned;")
#define TCGEN05_COMMIT(mbar) \
    asm volatile("tcgen05.commit.cta_group::1.mbarrier::arrive::one.shared::cluster.b64 [%0];" \
        :: "r"((uint32_t)(mbar)) : "memory")
#define TCGEN05_WAIT_LD() asm volatile("tcgen05.wait::ld.sync.aligned;" ::: "memory")
#define TCGEN05_FENCE_AFTER()  asm volatile("tcgen05.fence::after_thread_sync;" ::: "memory")
#define FENCE_PROXY_ASYNC_SHARED_CTA() \
    asm volatile("fence.proxy.async.shared::cta;" ::: "memory")
#define MBARRIER_INIT(mbar, count) \
    asm volatile("mbarrier.init.shared.b64 [%0], %1;" \
        :: "r"((uint32_t)(mbar)), "r"((uint32_t)(count)) : "memory")
#define MBARRIER_EXPECT_TX(mbar, tx_bytes) \
    asm volatile("mbarrier.arrive.expect_tx.shared.b64 _, [%0], %1;" \
        :: "r"((uint32_t)(mbar)), "r"((uint32_t)(tx_bytes)) : "memory")

#define MBARRIER_WAIT_PARITY(mbar_smem_addr, phase_parity) do { \
    uint32_t _mbar = (uint32_t)(mbar_smem_addr); \
    uint32_t _parity = (uint32_t)(phase_parity); \
    uint32_t _done; \
    asm volatile( \
        "{\n\t.reg .pred p;\n\t" \
        "mbarrier.try_wait.parity.acquire.cta.shared::cta.b64 p, [%1], %2;\n\t" \
        "selp.b32 %0, 1, 0, p;\n\t}" \
        : "=r"(_done) : "r"(_mbar), "r"(_parity) : "memory"); \
    if (!_done) { \
        asm volatile( \
            "{\n\t.reg .pred P1;\n\t" \
            "WAIT_LOOP_%=:\n\t" \
            "mbarrier.try_wait.parity.acquire.cta.shared::cta.b64 P1, [%0], %1, 0x989680;\n\t" \
            "@P1 bra.uni WAIT_DONE_%=;\n\t" \
            "bra.uni WAIT_LOOP_%=;\n\t" \
            "WAIT_DONE_%=:\n\t}" \
            :: "r"(_mbar), "r"(_parity) : "memory"); \
    } \
} while(0)

#define TCGEN05_LD_32X32B_X32(r, tmem_addr) \
    asm volatile( \
        "tcgen05.ld.sync.aligned.32x32b.x32.b32 " \
        "{%0, %1, %2, %3, %4, %5, %6, %7, " \
        " %8, %9, %10, %11, %12, %13, %14, %15, " \
        " %16, %17, %18, %19, %20, %21, %22, %23, " \
        " %24, %25, %26, %27, %28, %29, %30, %31}, [%32];" \
        : "=r"((r)[0]),  "=r"((r)[1]),  "=r"((r)[2]),  "=r"((r)[3]), \
          "=r"((r)[4]),  "=r"((r)[5]),  "=r"((r)[6]),  "=r"((r)[7]), \
          "=r"((r)[8]),  "=r"((r)[9]),  "=r"((r)[10]), "=r"((r)[11]), \
          "=r"((r)[12]), "=r"((r)[13]), "=r"((r)[14]), "=r"((r)[15]), \
          "=r"((r)[16]), "=r"((r)[17]), "=r"((r)[18]), "=r"((r)[19]), \
          "=r"((r)[20]), "=r"((r)[21]), "=r"((r)[22]), "=r"((r)[23]), \
          "=r"((r)[24]), "=r"((r)[25]), "=r"((r)[26]), "=r"((r)[27]), \
          "=r"((r)[28]), "=r"((r)[29]), "=r"((r)[30]), "=r"((r)[31]) \
        : "r"(tmem_addr))

#if HAS_TCGEN05
static __device__ __forceinline__ void mma_bf16_ss(uint32_t d_tmem, uint64_t a_desc,
                                                   uint64_t b_desc, uint32_t enable) {
    asm volatile(
        "{\n\t"
        ".reg .pred p;\n\t"
        "setp.ne.u32 p, %5, 0;\n\t"
        "tcgen05.mma.cta_group::1.kind::f16 [%0], %1, %2, %3, {%4, %4, %4, %4}, p;\n\t"
        "}"
        :: "r"(d_tmem), "l"(a_desc), "l"(b_desc), "r"(MMA_IDESC), "r"(0u), "r"(enable)
        : "memory");
}
static __device__ __forceinline__ void bulk_g2s(uint32_t dst_smem, const void* src,
                                                uint32_t bytes, uint32_t mbar) {
    asm volatile(
        "cp.async.bulk.shared::cluster.global.mbarrier::complete_tx::bytes "
        "[%0], [%1], %2, [%3];"
        :: "r"(dst_smem), "l"(src), "r"(bytes), "r"(mbar) : "memory");
}
static __device__ __forceinline__ void cp_async16(uint32_t dst_smem, const void* src) {
    asm volatile("cp.async.cg.shared.global [%0], [%1], 16;"
                 :: "r"(dst_smem), "l"(src) : "memory");
}
#define CP_ASYNC_COMMIT() asm volatile("cp.async.commit_group;" ::: "memory")
#define CP_ASYNC_WAIT_2() asm volatile("cp.async.wait_group 2;" ::: "memory")
#define CP_ASYNC_WAIT_1() asm volatile("cp.async.wait_group 1;" ::: "memory")
#define CP_ASYNC_WAIT_0() asm volatile("cp.async.wait_group 0;" ::: "memory")

static __device__ __forceinline__ void split2(float x0, float x1,
                                              uint32_t& hi01, uint32_t& lo01) {
    uint32_t h;
    asm("cvt.rn.bf16x2.f32 %0, %1, %2;" : "=r"(h) : "f"(x1), "f"(x0));
    float hf0 = __uint_as_float(h << 16);
    float hf1 = __uint_as_float(h & 0xFFFF0000u);
    float r0 = x0 - hf0;
    float r1 = x1 - hf1;
    uint32_t l;
    asm("cvt.rn.bf16x2.f32 %0, %1, %2;" : "=r"(l) : "f"(r1), "f"(r0));
    hi01 = h; lo01 = l;
}
#endif

static __device__ __forceinline__ int load_type(const void* ntype, long long r, int is64) {
    if (is64) return (int)((const long long*)ntype)[r];
    return ((const int*)ntype)[r];
}

// ============================================================================
// Kernel 1: detect node_type dtype (block 0) + split & pre-swizzle W.
// ============================================================================
__global__ void relemb_wsplit_kernel(const float* __restrict__ W,
                                     const unsigned int* __restrict__ t) {
    if (blockIdx.x == 0) {
        __shared__ int found;
        if (threadIdx.x == 0) found = 0;
        __syncthreads();
        for (int i = threadIdx.x; i < 4096; i += blockDim.x)
            if ((i & 1) && t[i] != 0u) found = 1;
        __syncthreads();
        if (threadIdx.x == 0) g_is64 = found ? 0 : 1;
    }
    int idx = blockIdx.x * 256 + threadIdx.x;
    float x = W[idx];
    __nv_bfloat16 hi = __float2bfloat16(x);
    __nv_bfloat16 lo = __float2bfloat16(x - __bfloat162float(hi));
    int j = idx >> 8;
    int k = idx & 255;
    int chunk = k >> 6, kk = k & 63;
    uint32_t byte = (uint32_t)chunk * 32768u + SW128((uint32_t)(j * 128 + kk * 2));
    *(__nv_bfloat16*)((char*)g_Whi + byte) = hi;
    *(__nv_bfloat16*)((char*)g_Wlo + byte) = lo;
}

// ============================================================================
// Kernel 2: per-256-row (tile pair) GEMM + select
// ============================================================================
__global__ __launch_bounds__(256, 1) void relemb_gemm_kernel(
    const float* __restrict__ emb,
    const void*  __restrict__ ntype,
    const float* __restrict__ W,      // fp32 W (fallback path only)
    const float* __restrict__ bias,
    float* __restrict__ out,
    int nrows)
{
#if HAS_TCGEN05
    extern __shared__ char smem[];
    const uint32_t sb = smem_u32(smem);
    const int tid = threadIdx.x;
    const int wid = tid >> 5;
    const int lid = tid & 31;
    const long long cta_base = (long long)blockIdx.x * 256;   // 2 tiles of 128
    const int is64 = g_is64;

    // ---------------- prologue ----------------
    if (tid == 0) {
        #pragma unroll
        for (int s = 0; s < 8; s++) MBARRIER_INIT(sb + MB_COMMIT + s * 8, 1);
        #pragma unroll
        for (int c = 0; c < 4; c++) MBARRIER_INIT(sb + MB_WFULL + c * 8, 1);
    }
    if (wid == 0) TCGEN05_ALLOC(sb + SMEM_TMEM_PTR, 512);
    ((float*)(smem + SMEM_BIAS))[tid] = bias[tid];
    {   // row types for both tiles (256 rows, stored as bytes)
        long long rg = cta_base + tid;
        int ty = (rg < nrows) ? load_type(ntype, rg, is64) : 0;
        ((unsigned char*)(smem + SMEM_TMASK))[tid] = (unsigned char)ty;
    }

    // prefetch A for steps 0 and 1 (depth-2 pipeline warmup)
    #pragma unroll
    for (int x = 0; x < 2; x++) {       // step x: chunk 0, tile x
        const long long ptb = cta_base + (long long)x * TILE_M;
        const uint32_t nb = sb + SMEM_A + (uint32_t)x * 32768u;
        #pragma unroll
        for (int i = 0; i < 4; ++i) {
            const int u = i * 256 + tid;
            const int row = u >> 3, seg = u & 7;
            const long long rg = ptb + row;
            if (rg < nrows) {
                const float* gp = emb + rg * D_DIM + seg * 8;
                const uint32_t dp = nb + (uint32_t)(row * 256 + seg * 32);
                cp_async16(dp, gp);
                cp_async16(dp + 16, gp + 4);
            }
        }
        CP_ASYNC_COMMIT();
    }
    __syncthreads();

    uint32_t tmem;
    asm volatile("ld.shared.b32 %0, [%1];" : "=r"(tmem) : "r"(sb + SMEM_TMEM_PTR));
    const unsigned char* tmask = (const unsigned char*)(smem + SMEM_TMASK);

    // ---------------- main loop: 8 steps = (chunk c = s>>1, tile t = s&1) ----
    #pragma unroll 1
    for (int s = 0; s < 8; s++) {
        const int c = s >> 1;
        const int t = s & 1;
        const long long tile_base = cta_base + (long long)t * TILE_M;

        // A buf (s+2)&3 == (s-2)&3 reuse: MMAs of step s-2 must be done.
        if (s >= 2) MBARRIER_WAIT_PARITY(sb + MB_COMMIT + (s - 2) * 8, 0);

        const uint32_t aBuf = SMEM_A + (uint32_t)(s & 3) * 32768u;  // hi +0, lo +16384
        const uint32_t wHi  = SMEM_W;
        const uint32_t wLo  = wHi + 32768u;

        // --- W chunk via bulk DMA, once per chunk (t==0 steps, tid0 only).
        // Single W buffer: overwrite needs MMAs of step s-1 (chunk c-1) done.
        // tid0-only wait; the other 255 threads proceed with prefetch/convert.
        if (t == 0 && tid == 0) {
            if (s >= 2) MBARRIER_WAIT_PARITY(sb + MB_COMMIT + (s - 1) * 8, 0);
            const uint32_t wfb = sb + MB_WFULL + c * 8;
            MBARRIER_EXPECT_TX(wfb, 65536u);
            bulk_g2s(sb + wHi, (const char*)g_Whi + c * 32768, 32768u, wfb);
            bulk_g2s(sb + wLo, (const char*)g_Wlo + c * 32768, 32768u, wfb);
        }

        // --- prefetch A for step s+2 into buf (s+2)&3 (depth-2) ---
        if (s < 6) {
            const int nc = (s + 2) >> 1, nt = (s + 2) & 1;
            const long long ntb = cta_base + (long long)nt * TILE_M;
            const uint32_t nb = sb + SMEM_A + (uint32_t)((s + 2) & 3) * 32768u;
            #pragma unroll
            for (int i = 0; i < 4; ++i) {
                const int u = i * 256 + tid;
                const int row = u >> 3, seg = u & 7;
                const long long rg = ntb + row;
                if (rg < nrows) {
                    const float* gp = emb + rg * D_DIM + nc * 64 + seg * 8;
                    const uint32_t dp = nb + (uint32_t)(row * 256 + seg * 32);
                    cp_async16(dp, gp);
                    cp_async16(dp + 16, gp + 4);
                }
            }
            CP_ASYNC_COMMIT();
        }

        // --- wait for step s's A staging (groups s+1, s+2 may stay pending) ---
        if (s < 6)      { CP_ASYNC_WAIT_2(); }
        else if (s == 6){ CP_ASYNC_WAIT_1(); }
        else            { CP_ASYNC_WAIT_0(); }

        // --- read phase: drain fp32 segs; entity rows -> STG out ---
        float4 st[8];
        #pragma unroll
        for (int i = 0; i < 4; ++i) {
            const int u = i * 256 + tid;
            const int row = u >> 3, seg = u & 7;
            const char* sp = smem + aBuf + (uint32_t)(row * 256 + seg * 32);
            st[2 * i]     = *(const float4*)sp;
            st[2 * i + 1] = *(const float4*)(sp + 16);
            const long long rg = tile_base + row;
            if (rg < nrows && tmask[t * TILE_M + row] == 0) {
                float4* dst = (float4*)(out + rg * D_DIM + c * 64 + seg * 8);
                dst[0] = st[2 * i];
                dst[1] = st[2 * i + 1];
            }
        }
        __syncthreads();   // separate in-place read from write

        // --- write phase: split relation rows -> swizzled bf16 hi|lo ---
        #pragma unroll
        for (int i = 0; i < 4; ++i) {
            const int u = i * 256 + tid;
            const int row = u >> 3, seg = u & 7;
            const long long rg = tile_base + row;
            if (rg < nrows && tmask[t * TILE_M + row] == 1) {
                const float4 a0 = st[2 * i], a1 = st[2 * i + 1];
                uint32_t h0, h1, h2, h3, l0, l1, l2, l3;
                split2(a0.x, a0.y, h0, l0);
                split2(a0.z, a0.w, h1, l1);
                split2(a1.x, a1.y, h2, l2);
                split2(a1.z, a1.w, h3, l3);
                const uint32_t sw = SW128((uint32_t)(row * 128 + seg * 16));
                *(uint4*)(smem + aBuf + sw)          = make_uint4(h0, h1, h2, h3);
                *(uint4*)(smem + aBuf + 16384u + sw) = make_uint4(l0, l1, l2, l3);
            }
        }
        FENCE_PROXY_ASYNC_SHARED_CTA();
        __syncthreads();

        // --- 12 MMAs (hi*hi + hi*lo + lo*hi) into accumulator t, commit ---
        if (wid == 0) {
            if (elect_one()) {
                MBARRIER_WAIT_PARITY(sb + MB_WFULL + c * 8, 0);
                TCGEN05_FENCE_AFTER();
                const uint32_t dtm = tmem + (uint32_t)(t * 256);
                const uint64_t dAh = MAKE_SMEM_DESC(sb + aBuf);
                const uint64_t dAl = MAKE_SMEM_DESC(sb + aBuf + 16384u);
                const uint64_t dWh = MAKE_SMEM_DESC(sb + wHi);
                const uint64_t dWl = MAKE_SMEM_DESC(sb + wLo);
                uint32_t acc = (c != 0) ? 1u : 0u;
                #pragma unroll
                for (int m = 0; m < 4; m++) {
                    mma_bf16_ss(dtm, dAh + 2 * m, dWh + 2 * m, acc);
                    acc = 1u;
                }
                #pragma unroll
                for (int m = 0; m < 4; m++)
                    mma_bf16_ss(dtm, dAh + 2 * m, dWl + 2 * m, 1u);
                #pragma unroll
                for (int m = 0; m < 4; m++)
                    mma_bf16_ss(dtm, dAl + 2 * m, dWh + 2 * m, 1u);
                TCGEN05_COMMIT(sb + MB_COMMIT + s * 8);
            }
        }
    }

    // ---------------- epilogue: relation rows = D + b (both tiles) --------
    {
        const float* sbias = (const float*)(smem + SMEM_BIAS);
        const int row = (wid & 3) * 32 + lid;
        const int cb0 = (wid >> 2) * 128;       // warps 0-3: cols 0-127; 4-7: 128-255
        #pragma unroll 1
        for (int t = 0; t < 2; t++) {
            MBARRIER_WAIT_PARITY(sb + MB_COMMIT + (6 + t) * 8, 0);
            TCGEN05_FENCE_AFTER();
            const uint32_t ptm = tmem + (uint32_t)(t * 256);
            const long long rg = cta_base + (long long)t * TILE_M + row;
            const bool rel = (rg < nrows) &&
                (((const unsigned char*)(smem + SMEM_TMASK))[t * TILE_M + row] == 1);
            #pragma unroll
            for (int pair = 0; pair < 2; pair++) {
                const int col0 = cb0 + pair * 64;
                uint32_t dreg[64];
                TCGEN05_LD_32X32B_X32(dreg,      ptm + (uint32_t)col0);
                TCGEN05_LD_32X32B_X32(dreg + 32, ptm + (uint32_t)(col0 + 32));
                TCGEN05_WAIT_LD();
                if (rel) {
                    #pragma unroll
                    for (int i = 0; i < 16; i++) {
                        const int col = col0 + 4 * i;
                        float4 v;
                        v.x = __uint_as_float(dreg[4 * i + 0]) + sbias[col + 0];
                        v.y = __uint_as_float(dreg[4 * i + 1]) + sbias[col + 1];
                        v.z = __uint_as_float(dreg[4 * i + 2]) + sbias[col + 2];
                        v.w = __uint_as_float(dreg[4 * i + 3]) + sbias[col + 3];
                        *(float4*)(out + rg * D_DIM + col) = v;
                    }
                }
            }
        }
    }

    __syncthreads();
    if (wid == 0) {
        TCGEN05_RELINQUISH();
        TCGEN05_DEALLOC(tmem, 512);
    }
#else
    // ======================= SIMT fallback (plain compute_103 pass) ========
    extern __shared__ char smem[];
    float* se = (float*)smem;                          // 128 x 256 f32 tile
    int* sm_mask = (int*)(smem + TILE_M * D_DIM * 4);  // 128 ints
    const int tid = threadIdx.x;
    const int is64 = g_is64;

    #pragma unroll 1
    for (int t = 0; t < 2; t++) {
        const long long tile_base = (long long)blockIdx.x * 256 + (long long)t * TILE_M;
        if (tile_base >= nrows) break;
        __syncthreads();
        if (tid < TILE_M) {
            long long rg = tile_base + tid;
            sm_mask[tid] = (rg < nrows) ? load_type(ntype, rg, is64) : 0;
        }
        for (int i = tid; i < TILE_M * D_DIM; i += 256) {
            int r = i >> 8;
            long long rg = tile_base + r;
            se[i] = (rg < nrows) ? emb[rg * D_DIM + (i & 255)] : 0.f;
        }
        __syncthreads();

        const float bc = bias[tid];
        const float* wr = W + (long long)tid * D_DIM;
        for (int r = 0; r < TILE_M; r++) {
            long long rg = tile_base + r;
            if (rg >= nrows) break;
            if (sm_mask[r] == 1) {
                const float* er = se + r * D_DIM;
                float acc = 0.f;
                #pragma unroll 8
                for (int k = 0; k < D_DIM; k++) acc = fmaf(er[k], wr[k], acc);
                out[rg * D_DIM + tid] = acc + bc;
            } else {
                out[rg * D_DIM + tid] = se[r * D_DIM + tid];
            }
        }
    }
#endif
}

// ============================================================================
// launch — same structure as the passing R7/R9/R10 versions
// ============================================================================
extern "C" void kernel_launch(void* const* d_in, const int* in_sizes, int n_in,
                              void* d_out, int out_size) {
    const float* emb   = (const float*)d_in[0];
    const void*  ntype = d_in[1];
    const float* W     = (const float*)d_in[2];
    const float* b     = (const float*)d_in[3];
    float*       out   = (float*)d_out;
    const int nrows = in_sizes[1];

    relemb_wsplit_kernel<<<256, 256>>>(W, (const unsigned int*)ntype);

    cudaFuncSetAttribute(relemb_gemm_kernel,
                         cudaFuncAttributeMaxDynamicSharedMemorySize, SMEM_BYTES);
    const int ntiles = (nrows + TILE_M - 1) / TILE_M;
    const int npairs = (ntiles + 1) / 2;
    relemb_gemm_kernel<<<npairs, 256, SMEM_BYTES>>>(emb, ntype, W, b, out, nrows);
}

// round 12
// speedup vs baseline: 1.0505x; 1.0505x over previous
#include <cuda_runtime.h>
#include <cuda_bf16.h>
#include <cstdint>

// ============================================================================
// RelationEmbeddingUpdater: out = where(type==1, emb @ W^T + b, emb)
//
// One CTA (512 threads) per PAIR of 128-row tiles. bf16 2-way-split GEMM
// (3 MMA passes ~ fp32 accuracy), fp32 accum in TMEM (two 256-col accums).
// Chunk-outer, tile-inner loop; W staged once per chunk (2 W buffers).
//  - A staged via cp.async depth-1 (R10-proven), 3 rotating 32KB buffers,
//    converted IN PLACE (regs across a barrier).
//  - 16 warps: halves per-thread latency chains vs 256 threads; epilogue
//    drains tile0/tile1 in parallel (warps 0-7 / 8-15).
//  - relation-only fp32->bf16 split; entity rows passthrough from registers.
// ============================================================================

#define D_DIM 256
#define TILE_M 128
#define THREADS 512

// ---------------- smem layout (dynamic) ----------------
#define SMEM_TMEM_PTR 0
#define MB_COMMIT     16           // 8 mbarriers x 8B (per-step MMA commits), single-use
#define MB_WFULL      80           // 4 mbarriers x 8B (W DMA completion), single-use
#define SMEM_BIAS     128          // 256 floats
#define SMEM_TMASK    1152         // 256 bytes (row types for both tiles)
#define SMEM_A        2048         // 3 bufs x 32KB (fp32 staging -> in-place bf16 hi|lo)
#define SMEM_W        100352       // 2 bufs x (hi 32KB + lo 32KB) = 128KB (1024-aligned)
#define SMEM_BYTES    231424

// idesc kind::f16: dtype=F32, atype=BF16, btype=BF16, N=256, M=128, cg1
#define MMA_IDESC 0x8400490u

// Pre-split + PRE-SWIZZLED W: chunk c occupies bytes [c*32768,(c+1)*32768);
// element (j,kk) at SW128(j*128 + kk*2). Linear bulk copy into 1024-aligned
// smem preserves the swizzle (SW128 permutes bits [6:4] within 1024B blocks).
__device__ __align__(128) __nv_bfloat16 g_Whi[D_DIM * D_DIM];
__device__ __align__(128) __nv_bfloat16 g_Wlo[D_DIM * D_DIM];

// node_type dtype flag: 1 if int64, 0 if int32
__device__ int g_is64;

#if defined(__CUDA_ARCH_FEAT_SM103_ALL) || defined(__CUDA_ARCH_FEAT_SM100_ALL) || defined(__CUDA_ARCH_FEAT_SM101_ALL)
#define HAS_TCGEN05 1
#else
#define HAS_TCGEN05 0
#endif

// ---------------- helpers ----------------
static __device__ __forceinline__ uint32_t smem_u32(const void* p) {
    uint32_t a;
    asm("{ .reg .u64 t; cvta.to.shared.u64 t, %1; cvt.u32.u64 %0, t; }"
        : "=r"(a) : "l"(p));
    return a;
}
static __device__ __forceinline__ uint32_t elect_one() {
    uint32_t p;
    asm volatile("{ .reg .pred p; elect.sync _|p, 0xFFFFFFFF; selp.b32 %0, 1, 0, p; }"
                 : "=r"(p));
    return p;
}
#define SW128(o) ((o) ^ (((o) >> 3) & 0x70))

static constexpr uint64_t SMEM_DESC_BASE_SW128 =
    (uint64_t(2) << 61) | (uint64_t(1) << 46) | (uint64_t(64) << 32) | (uint64_t(1) << 16);
#define MAKE_SMEM_DESC(base_addr) \
    (SMEM_DESC_BASE_SW128 | ((uint64_t)((base_addr) >> 4) & 0x3FFF))

#define TCGEN05_ALLOC(smem_addr, nCols) \
    asm volatile("tcgen05.alloc.cta_group::1.sync.aligned.shared::cta.b32 [%0], %1;" \
        :: "r"((uint32_t)(smem_addr)), "r"((uint32_t)(nCols)) : "memory")
#define TCGEN05_DEALLOC(tmem_addr, nCols) \
    asm volatile("tcgen05.dealloc.cta_group::1.sync.aligned.b32 %0, %1;" \
        :: "r"(tmem_addr), "r"((uint32_t)(nCols)))
#define TCGEN05_RELINQUISH() \
    asm volatile("tcgen05.relinquish_alloc_permit.cta_group::1.sync.aligned;")
#define TCGEN05_COMMIT(mbar) \
    asm volatile("tcgen05.commit.cta_group::1.mbarrier::arrive::one.shared::cluster.b64 [%0];" \
        :: "r"((uint32_t)(mbar)) : "memory")
#define TCGEN05_WAIT_LD() asm volatile("tcgen05.wait::ld.sync.aligned;" ::: "memory")
#define TCGEN05_FENCE_AFTER()  asm volatile("tcgen05.fence::after_thread_sync;" ::: "memory")
#define FENCE_PROXY_ASYNC_SHARED_CTA() \
    asm volatile("fence.proxy.async.shared::cta;" ::: "memory")
#define MBARRIER_INIT(mbar, count) \
    asm volatile("mbarrier.init.shared.b64 [%0], %1;" \
        :: "r"((uint32_t)(mbar)), "r"((uint32_t)(count)) : "memory")
#define MBARRIER_EXPECT_TX(mbar, tx_bytes) \
    asm volatile("mbarrier.arrive.expect_tx.shared.b64 _, [%0], %1;" \
        :: "r"((uint32_t)(mbar)), "r"((uint32_t)(tx_bytes)) : "memory")

#define MBARRIER_WAIT_PARITY(mbar_smem_addr, phase_parity) do { \
    uint32_t _mbar = (uint32_t)(mbar_smem_addr); \
    uint32_t _parity = (uint32_t)(phase_parity); \
    uint32_t _done; \
    asm volatile( \
        "{\n\t.reg .pred p;\n\t" \
        "mbarrier.try_wait.parity.acquire.cta.shared::cta.b64 p, [%1], %2;\n\t" \
        "selp.b32 %0, 1, 0, p;\n\t}" \
        : "=r"(_done) : "r"(_mbar), "r"(_parity) : "memory"); \
    if (!_done) { \
        asm volatile( \
            "{\n\t.reg .pred P1;\n\t" \
            "WAIT_LOOP_%=:\n\t" \
            "mbarrier.try_wait.parity.acquire.cta.shared::cta.b64 P1, [%0], %1, 0x989680;\n\t" \
            "@P1 bra.uni WAIT_DONE_%=;\n\t" \
            "bra.uni WAIT_LOOP_%=;\n\t" \
            "WAIT_DONE_%=:\n\t}" \
            :: "r"(_mbar), "r"(_parity) : "memory"); \
    } \
} while(0)

#define TCGEN05_LD_32X32B_X32(r, tmem_addr) \
    asm volatile( \
        "tcgen05.ld.sync.aligned.32x32b.x32.b32 " \
        "{%0, %1, %2, %3, %4, %5, %6, %7, " \
        " %8, %9, %10, %11, %12, %13, %14, %15, " \
        " %16, %17, %18, %19, %20, %21, %22, %23, " \
        " %24, %25, %26, %27, %28, %29, %30, %31}, [%32];" \
        : "=r"((r)[0]),  "=r"((r)[1]),  "=r"((r)[2]),  "=r"((r)[3]), \
          "=r"((r)[4]),  "=r"((r)[5]),  "=r"((r)[6]),  "=r"((r)[7]), \
          "=r"((r)[8]),  "=r"((r)[9]),  "=r"((r)[10]), "=r"((r)[11]), \
          "=r"((r)[12]), "=r"((r)[13]), "=r"((r)[14]), "=r"((r)[15]), \
          "=r"((r)[16]), "=r"((r)[17]), "=r"((r)[18]), "=r"((r)[19]), \
          "=r"((r)[20]), "=r"((r)[21]), "=r"((r)[22]), "=r"((r)[23]), \
          "=r"((r)[24]), "=r"((r)[25]), "=r"((r)[26]), "=r"((r)[27]), \
          "=r"((r)[28]), "=r"((r)[29]), "=r"((r)[30]), "=r"((r)[31]) \
        : "r"(tmem_addr))

#if HAS_TCGEN05
static __device__ __forceinline__ void mma_bf16_ss(uint32_t d_tmem, uint64_t a_desc,
                                                   uint64_t b_desc, uint32_t enable) {
    asm volatile(
        "{\n\t"
        ".reg .pred p;\n\t"
        "setp.ne.u32 p, %5, 0;\n\t"
        "tcgen05.mma.cta_group::1.kind::f16 [%0], %1, %2, %3, {%4, %4, %4, %4}, p;\n\t"
        "}"
        :: "r"(d_tmem), "l"(a_desc), "l"(b_desc), "r"(MMA_IDESC), "r"(0u), "r"(enable)
        : "memory");
}
static __device__ __forceinline__ void bulk_g2s(uint32_t dst_smem, const void* src,
                                                uint32_t bytes, uint32_t mbar) {
    asm volatile(
        "cp.async.bulk.shared::cluster.global.mbarrier::complete_tx::bytes "
        "[%0], [%1], %2, [%3];"
        :: "r"(dst_smem), "l"(src), "r"(bytes), "r"(mbar) : "memory");
}
static __device__ __forceinline__ void cp_async16(uint32_t dst_smem, const void* src) {
    asm volatile("cp.async.cg.shared.global [%0], [%1], 16;"
                 :: "r"(dst_smem), "l"(src) : "memory");
}
#define CP_ASYNC_COMMIT() asm volatile("cp.async.commit_group;" ::: "memory")
#define CP_ASYNC_WAIT_1() asm volatile("cp.async.wait_group 1;" ::: "memory")
#define CP_ASYNC_WAIT_0() asm volatile("cp.async.wait_group 0;" ::: "memory")

static __device__ __forceinline__ void split2(float x0, float x1,
                                              uint32_t& hi01, uint32_t& lo01) {
    uint32_t h;
    asm("cvt.rn.bf16x2.f32 %0, %1, %2;" : "=r"(h) : "f"(x1), "f"(x0));
    float hf0 = __uint_as_float(h << 16);
    float hf1 = __uint_as_float(h & 0xFFFF0000u);
    float r0 = x0 - hf0;
    float r1 = x1 - hf1;
    uint32_t l;
    asm("cvt.rn.bf16x2.f32 %0, %1, %2;" : "=r"(l) : "f"(r1), "f"(r0));
    hi01 = h; lo01 = l;
}
#endif

static __device__ __forceinline__ int load_type(const void* ntype, long long r, int is64) {
    if (is64) return (int)((const long long*)ntype)[r];
    return ((const int*)ntype)[r];
}

// ============================================================================
// Kernel 1: detect node_type dtype (block 0) + split & pre-swizzle W.
// ============================================================================
__global__ void relemb_wsplit_kernel(const float* __restrict__ W,
                                     const unsigned int* __restrict__ t) {
    if (blockIdx.x == 0) {
        __shared__ int found;
        if (threadIdx.x == 0) found = 0;
        __syncthreads();
        for (int i = threadIdx.x; i < 4096; i += blockDim.x)
            if ((i & 1) && t[i] != 0u) found = 1;
        __syncthreads();
        if (threadIdx.x == 0) g_is64 = found ? 0 : 1;
    }
    int idx = blockIdx.x * 256 + threadIdx.x;
    float x = W[idx];
    __nv_bfloat16 hi = __float2bfloat16(x);
    __nv_bfloat16 lo = __float2bfloat16(x - __bfloat162float(hi));
    int j = idx >> 8;
    int k = idx & 255;
    int chunk = k >> 6, kk = k & 63;
    uint32_t byte = (uint32_t)chunk * 32768u + SW128((uint32_t)(j * 128 + kk * 2));
    *(__nv_bfloat16*)((char*)g_Whi + byte) = hi;
    *(__nv_bfloat16*)((char*)g_Wlo + byte) = lo;
}

// ============================================================================
// Kernel 2: per-256-row (tile pair) GEMM + select, 512 threads
// ============================================================================
__global__ __launch_bounds__(THREADS, 1) void relemb_gemm_kernel(
    const float* __restrict__ emb,
    const void*  __restrict__ ntype,
    const float* __restrict__ W,      // fp32 W (fallback path only)
    const float* __restrict__ bias,
    float* __restrict__ out,
    int nrows)
{
#if HAS_TCGEN05
    extern __shared__ char smem[];
    const uint32_t sb = smem_u32(smem);
    const int tid = threadIdx.x;
    const int wid = tid >> 5;
    const int lid = tid & 31;
    const long long cta_base = (long long)blockIdx.x * 256;   // 2 tiles of 128
    const int is64 = g_is64;

    // ---------------- prologue ----------------
    if (tid == 0) {
        #pragma unroll
        for (int s = 0; s < 8; s++) MBARRIER_INIT(sb + MB_COMMIT + s * 8, 1);
        #pragma unroll
        for (int c = 0; c < 4; c++) MBARRIER_INIT(sb + MB_WFULL + c * 8, 1);
    }
    if (wid == 0) TCGEN05_ALLOC(sb + SMEM_TMEM_PTR, 512);
    if (tid < 256) {
        ((float*)(smem + SMEM_BIAS))[tid] = bias[tid];
        long long rg = cta_base + tid;
        int ty = (rg < nrows) ? load_type(ntype, rg, is64) : 0;
        ((unsigned char*)(smem + SMEM_TMASK))[tid] = (unsigned char)ty;
    }

    // prefetch A for step 0 (chunk 0, tile 0) into buf 0
    {
        const uint32_t ab = sb + SMEM_A;
        #pragma unroll
        for (int i = 0; i < 2; ++i) {
            const int u = i * THREADS + tid;      // 0..1023 (32B segments)
            const int row = u >> 3, seg = u & 7;
            const long long rg = cta_base + row;
            if (rg < nrows) {
                const float* gp = emb + rg * D_DIM + seg * 8;
                const uint32_t dp = ab + (uint32_t)(row * 256 + seg * 32);
                cp_async16(dp, gp);
                cp_async16(dp + 16, gp + 4);
            }
        }
        CP_ASYNC_COMMIT();
    }
    __syncthreads();

    uint32_t tmem;
    asm volatile("ld.shared.b32 %0, [%1];" : "=r"(tmem) : "r"(sb + SMEM_TMEM_PTR));
    const unsigned char* tmask = (const unsigned char*)(smem + SMEM_TMASK);

    // ---------------- main loop: 8 steps = (chunk c = s>>1, tile t = s&1) ----
    #pragma unroll 1
    for (int s = 0; s < 8; s++) {
        const int c = s >> 1;
        const int t = s & 1;
        const long long tile_base = cta_base + (long long)t * TILE_M;

        // buffer reuse: A buf s%3 (and W buf for t==0 steps) last read by
        // step s-2's MMAs; commits are in-order so commit s-2 suffices.
        if (s >= 2) MBARRIER_WAIT_PARITY(sb + MB_COMMIT + (s - 2) * 8, 0);

        const uint32_t aBuf = SMEM_A + (uint32_t)(s % 3) * 32768u;  // hi +0, lo +16384
        const uint32_t wHi  = SMEM_W + (uint32_t)(c & 1) * 65536u;
        const uint32_t wLo  = wHi + 32768u;

        // --- W chunk via bulk DMA, once per chunk (t==0 steps only) ---
        if (t == 0 && tid == 0) {
            const uint32_t wfb = sb + MB_WFULL + c * 8;
            MBARRIER_EXPECT_TX(wfb, 65536u);
            bulk_g2s(sb + wHi, (const char*)g_Whi + c * 32768, 32768u, wfb);
            bulk_g2s(sb + wLo, (const char*)g_Wlo + c * 32768, 32768u, wfb);
        }

        // --- prefetch A for step s+1 into buf (s+1)%3 ---
        if (s < 7) {
            const int nc = (s + 1) >> 1, nt = (s + 1) & 1;
            const long long ntb = cta_base + (long long)nt * TILE_M;
            const uint32_t nb = sb + SMEM_A + (uint32_t)((s + 1) % 3) * 32768u;
            #pragma unroll
            for (int i = 0; i < 2; ++i) {
                const int u = i * THREADS + tid;
                const int row = u >> 3, seg = u & 7;
                const long long rg = ntb + row;
                if (rg < nrows) {
                    const float* gp = emb + rg * D_DIM + nc * 64 + seg * 8;
                    const uint32_t dp = nb + (uint32_t)(row * 256 + seg * 32);
                    cp_async16(dp, gp);
                    cp_async16(dp + 16, gp + 4);
                }
            }
            CP_ASYNC_COMMIT();
        }

        // --- wait for step s's A staging ---
        if (s < 7) { CP_ASYNC_WAIT_1(); } else { CP_ASYNC_WAIT_0(); }

        // --- read phase: drain fp32 segs; entity rows -> STG out ---
        float4 st[4];
        #pragma unroll
        for (int i = 0; i < 2; ++i) {
            const int u = i * THREADS + tid;
            const int row = u >> 3, seg = u & 7;
            const char* sp = smem + aBuf + (uint32_t)(row * 256 + seg * 32);
            st[2 * i]     = *(const float4*)sp;
            st[2 * i + 1] = *(const float4*)(sp + 16);
            const long long rg = tile_base + row;
            if (rg < nrows && tmask[t * TILE_M + row] == 0) {
                float4* dst = (float4*)(out + rg * D_DIM + c * 64 + seg * 8);
                dst[0] = st[2 * i];
                dst[1] = st[2 * i + 1];
            }
        }
        __syncthreads();   // separate in-place read from write

        // --- write phase: split relation rows -> swizzled bf16 hi|lo ---
        #pragma unroll
        for (int i = 0; i < 2; ++i) {
            const int u = i * THREADS + tid;
            const int row = u >> 3, seg = u & 7;
            const long long rg = tile_base + row;
            if (rg < nrows && tmask[t * TILE_M + row] == 1) {
                const float4 a0 = st[2 * i], a1 = st[2 * i + 1];
                uint32_t h0, h1, h2, h3, l0, l1, l2, l3;
                split2(a0.x, a0.y, h0, l0);
                split2(a0.z, a0.w, h1, l1);
                split2(a1.x, a1.y, h2, l2);
                split2(a1.z, a1.w, h3, l3);
                const uint32_t sw = SW128((uint32_t)(row * 128 + seg * 16));
                *(uint4*)(smem + aBuf + sw)          = make_uint4(h0, h1, h2, h3);
                *(uint4*)(smem + aBuf + 16384u + sw) = make_uint4(l0, l1, l2, l3);
            }
        }
        FENCE_PROXY_ASYNC_SHARED_CTA();
        __syncthreads();

        // --- 12 MMAs (hi*hi + hi*lo + lo*hi) into accumulator t, commit ---
        if (wid == 0) {
            if (elect_one()) {
                MBARRIER_WAIT_PARITY(sb + MB_WFULL + c * 8, 0);
                TCGEN05_FENCE_AFTER();
                const uint32_t dtm = tmem + (uint32_t)(t * 256);
                const uint64_t dAh = MAKE_SMEM_DESC(sb + aBuf);
                const uint64_t dAl = MAKE_SMEM_DESC(sb + aBuf + 16384u);
                const uint64_t dWh = MAKE_SMEM_DESC(sb + wHi);
                const uint64_t dWl = MAKE_SMEM_DESC(sb + wLo);
                uint32_t acc = (c != 0) ? 1u : 0u;
                #pragma unroll
                for (int m = 0; m < 4; m++) {
                    mma_bf16_ss(dtm, dAh + 2 * m, dWh + 2 * m, acc);
                    acc = 1u;
                }
                #pragma unroll
                for (int m = 0; m < 4; m++)
                    mma_bf16_ss(dtm, dAh + 2 * m, dWl + 2 * m, 1u);
                #pragma unroll
                for (int m = 0; m < 4; m++)
                    mma_bf16_ss(dtm, dAl + 2 * m, dWh + 2 * m, 1u);
                TCGEN05_COMMIT(sb + MB_COMMIT + s * 8);
            }
        }
    }

    // ------- epilogue: both tiles in parallel (warps 0-7: t0, 8-15: t1) ----
    {
        const float* sbias = (const float*)(smem + SMEM_BIAS);
        const int t = wid >> 3;                     // tile
        const int row = (wid & 3) * 32 + lid;
        const int cb0 = ((wid >> 2) & 1) * 128;     // col half
        MBARRIER_WAIT_PARITY(sb + MB_COMMIT + (6 + t) * 8, 0);
        TCGEN05_FENCE_AFTER();
        const uint32_t ptm = tmem + (uint32_t)(t * 256);
        const long long rg = cta_base + (long long)t * TILE_M + row;
        const bool rel = (rg < nrows) &&
            (((const unsigned char*)(smem + SMEM_TMASK))[t * TILE_M + row] == 1);
        #pragma unroll
        for (int pair = 0; pair < 2; pair++) {
            const int col0 = cb0 + pair * 64;
            uint32_t dreg[64];
            TCGEN05_LD_32X32B_X32(dreg,      ptm + (uint32_t)col0);
            TCGEN05_LD_32X32B_X32(dreg + 32, ptm + (uint32_t)(col0 + 32));
            TCGEN05_WAIT_LD();
            if (rel) {
                #pragma unroll
                for (int i = 0; i < 16; i++) {
                    const int col = col0 + 4 * i;
                    float4 v;
                    v.x = __uint_as_float(dreg[4 * i + 0]) + sbias[col + 0];
                    v.y = __uint_as_float(dreg[4 * i + 1]) + sbias[col + 1];
                    v.z = __uint_as_float(dreg[4 * i + 2]) + sbias[col + 2];
                    v.w = __uint_as_float(dreg[4 * i + 3]) + sbias[col + 3];
                    *(float4*)(out + rg * D_DIM + col) = v;
                }
            }
        }
    }

    __syncthreads();
    if (wid == 0) {
        TCGEN05_RELINQUISH();
        TCGEN05_DEALLOC(tmem, 512);
    }
#else
    // ======================= SIMT fallback (plain compute_103 pass) ========
    extern __shared__ char smem[];
    float* se = (float*)smem;                          // 128 x 256 f32 tile
    int* sm_mask = (int*)(smem + TILE_M * D_DIM * 4);  // 128 ints
    const int tid = threadIdx.x;
    const int is64 = g_is64;

    #pragma unroll 1
    for (int t = 0; t < 2; t++) {
        const long long tile_base = (long long)blockIdx.x * 256 + (long long)t * TILE_M;
        if (tile_base >= nrows) break;
        __syncthreads();
        if (tid < TILE_M) {
            long long rg = tile_base + tid;
            sm_mask[tid] = (rg < nrows) ? load_type(ntype, rg, is64) : 0;
        }
        for (int i = tid; i < TILE_M * D_DIM; i += THREADS) {
            int r = i >> 8;
            long long rg = tile_base + r;
            se[i] = (rg < nrows) ? emb[rg * D_DIM + (i & 255)] : 0.f;
        }
        __syncthreads();

        if (tid < 256) {
            const float bc = bias[tid];
            const float* wr = W + (long long)tid * D_DIM;
            for (int r = 0; r < TILE_M; r++) {
                long long rg = tile_base + r;
                if (rg >= nrows) break;
                if (sm_mask[r] == 1) {
                    const float* er = se + r * D_DIM;
                    float acc = 0.f;
                    #pragma unroll 8
                    for (int k = 0; k < D_DIM; k++) acc = fmaf(er[k], wr[k], acc);
                    out[rg * D_DIM + tid] = acc + bc;
                } else {
                    out[rg * D_DIM + tid] = se[r * D_DIM + tid];
                }
            }
        }
    }
#endif
}

// ============================================================================
// launch — same structure as the passing R7/R9/R10 versions
// ============================================================================
extern "C" void kernel_launch(void* const* d_in, const int* in_sizes, int n_in,
                              void* d_out, int out_size) {
    const float* emb   = (const float*)d_in[0];
    const void*  ntype = d_in[1];
    const float* W     = (const float*)d_in[2];
    const float* b     = (const float*)d_in[3];
    float*       out   = (float*)d_out;
    const int nrows = in_sizes[1];

    relemb_wsplit_kernel<<<256, 256>>>(W, (const unsigned int*)ntype);

    cudaFuncSetAttribute(relemb_gemm_kernel,
                         cudaFuncAttributeMaxDynamicSharedMemorySize, SMEM_BYTES);
    const int ntiles = (nrows + TILE_M - 1) / TILE_M;
    const int npairs = (ntiles + 1) / 2;
    relemb_gemm_kernel<<<npairs, THREADS, SMEM_BYTES>>>(emb, ntype, W, b, out, nrows);
}

// round 13
// speedup vs baseline: 1.0539x; 1.0033x over previous
#include <cuda_runtime.h>
#include <cuda_bf16.h>
#include <cstdint>

// ============================================================================
// RelationEmbeddingUpdater: out = where(type==1, emb @ W^T + b, emb)
//
// One CTA (512 threads) per PAIR of 128-row tiles. bf16 2-way-split GEMM
// (3 MMA passes ~ fp32 accuracy), fp32 accum in TMEM (two 256-col accums).
// Chunk-outer, tile-inner loop; W staged once per chunk.
//  - A staged via cp.async depth-1, OUT-OF-PLACE conversion: fp32 staging
//    (2x32KB) -> bf16 hi|lo output buffers (2x32KB). ONE barrier per step
//    (was two with in-place), convert streams LDS->split->STS per segment.
//  - W: single 64KB buffer; overwrite guarded by tid0-only commit(s-1) wait
//    at even steps (lands ~when other threads reach the step barrier).
//  - relation-only fp32->bf16 split; entity rows passthrough from registers.
// ============================================================================

#define D_DIM 256
#define TILE_M 128
#define THREADS 512

// ---------------- smem layout (dynamic) ----------------
#define SMEM_TMEM_PTR 0
#define MB_COMMIT     16           // 8 mbarriers x 8B (per-step MMA commits), single-use
#define MB_WFULL      80           // 4 mbarriers x 8B (W DMA completion), single-use
#define SMEM_BIAS     128          // 256 floats
#define SMEM_TMASK    1152         // 256 bytes (row types for both tiles)
#define SMEM_A        2048         // 2 bufs x 32KB fp32 staging
#define SMEM_O        67584        // 2 bufs x 32KB bf16 out (hi 16KB | lo 16KB)
#define SMEM_W        133120       // 1 buf: hi 32KB + lo 32KB (1024-aligned)
#define SMEM_BYTES    198656

// idesc kind::f16: dtype=F32, atype=BF16, btype=BF16, N=256, M=128, cg1
#define MMA_IDESC 0x8400490u

// Pre-split + PRE-SWIZZLED W: chunk c occupies bytes [c*32768,(c+1)*32768);
// element (j,kk) at SW128(j*128 + kk*2). Linear bulk copy into 1024-aligned
// smem preserves the swizzle (SW128 permutes bits [6:4] within 1024B blocks).
__device__ __align__(128) __nv_bfloat16 g_Whi[D_DIM * D_DIM];
__device__ __align__(128) __nv_bfloat16 g_Wlo[D_DIM * D_DIM];

// node_type dtype flag: 1 if int64, 0 if int32
__device__ int g_is64;

#if defined(__CUDA_ARCH_FEAT_SM103_ALL) || defined(__CUDA_ARCH_FEAT_SM100_ALL) || defined(__CUDA_ARCH_FEAT_SM101_ALL)
#define HAS_TCGEN05 1
#else
#define HAS_TCGEN05 0
#endif

// ---------------- helpers ----------------
static __device__ __forceinline__ uint32_t smem_u32(const void* p) {
    uint32_t a;
    asm("{ .reg .u64 t; cvta.to.shared.u64 t, %1; cvt.u32.u64 %0, t; }"
        : "=r"(a) : "l"(p));
    return a;
}
static __device__ __forceinline__ uint32_t elect_one() {
    uint32_t p;
    asm volatile("{ .reg .pred p; elect.sync _|p, 0xFFFFFFFF; selp.b32 %0, 1, 0, p; }"
                 : "=r"(p));
    return p;
}
#define SW128(o) ((o) ^ (((o) >> 3) & 0x70))

static constexpr uint64_t SMEM_DESC_BASE_SW128 =
    (uint64_t(2) << 61) | (uint64_t(1) << 46) | (uint64_t(64) << 32) | (uint64_t(1) << 16);
#define MAKE_SMEM_DESC(base_addr) \
    (SMEM_DESC_BASE_SW128 | ((uint64_t)((base_addr) >> 4) & 0x3FFF))

#define TCGEN05_ALLOC(smem_addr, nCols) \
    asm volatile("tcgen05.alloc.cta_group::1.sync.aligned.shared::cta.b32 [%0], %1;" \
        :: "r"((uint32_t)(smem_addr)), "r"((uint32_t)(nCols)) : "memory")
#define TCGEN05_DEALLOC(tmem_addr, nCols) \
    asm volatile("tcgen05.dealloc.cta_group::1.sync.aligned.b32 %0, %1;" \
        :: "r"(tmem_addr), "r"((uint32_t)(nCols)))
#define TCGEN05_RELINQUISH() \
    asm volatile("tcgen05.relinquish_alloc_permit.cta_group::1.sync.aligned;")
#define TCGEN05_COMMIT(mbar) \
    asm volatile("tcgen05.commit.cta_group::1.mbarrier::arrive::one.shared::cluster.b64 [%0];" \
        :: "r"((uint32_t)(mbar)) : "memory")
#define TCGEN05_WAIT_LD() asm volatile("tcgen05.wait::ld.sync.aligned;" ::: "memory")
#define TCGEN05_FENCE_AFTER()  asm volatile("tcgen05.fence::after_thread_sync;" ::: "memory")
#define FENCE_PROXY_ASYNC_SHARED_CTA() \
    asm volatile("fence.proxy.async.shared::cta;" ::: "memory")
#define MBARRIER_INIT(mbar, count) \
    asm volatile("mbarrier.init.shared.b64 [%0], %1;" \
        :: "r"((uint32_t)(mbar)), "r"((uint32_t)(count)) : "memory")
#define MBARRIER_EXPECT_TX(mbar, tx_bytes) \
    asm volatile("mbarrier.arrive.expect_tx.shared.b64 _, [%0], %1;" \
        :: "r"((uint32_t)(mbar)), "r"((uint32_t)(tx_bytes)) : "memory")

#define MBARRIER_WAIT_PARITY(mbar_smem_addr, phase_parity) do { \
    uint32_t _mbar = (uint32_t)(mbar_smem_addr); \
    uint32_t _parity = (uint32_t)(phase_parity); \
    uint32_t _done; \
    asm volatile( \
        "{\n\t.reg .pred p;\n\t" \
        "mbarrier.try_wait.parity.acquire.cta.shared::cta.b64 p, [%1], %2;\n\t" \
        "selp.b32 %0, 1, 0, p;\n\t}" \
        : "=r"(_done) : "r"(_mbar), "r"(_parity) : "memory"); \
    if (!_done) { \
        asm volatile( \
            "{\n\t.reg .pred P1;\n\t" \
            "WAIT_LOOP_%=:\n\t" \
            "mbarrier.try_wait.parity.acquire.cta.shared::cta.b64 P1, [%0], %1, 0x989680;\n\t" \
            "@P1 bra.uni WAIT_DONE_%=;\n\t" \
            "bra.uni WAIT_LOOP_%=;\n\t" \
            "WAIT_DONE_%=:\n\t}" \
            :: "r"(_mbar), "r"(_parity) : "memory"); \
    } \
} while(0)

#define TCGEN05_LD_32X32B_X32(r, tmem_addr) \
    asm volatile( \
        "tcgen05.ld.sync.aligned.32x32b.x32.b32 " \
        "{%0, %1, %2, %3, %4, %5, %6, %7, " \
        " %8, %9, %10, %11, %12, %13, %14, %15, " \
        " %16, %17, %18, %19, %20, %21, %22, %23, " \
        " %24, %25, %26, %27, %28, %29, %30, %31}, [%32];" \
        : "=r"((r)[0]),  "=r"((r)[1]),  "=r"((r)[2]),  "=r"((r)[3]), \
          "=r"((r)[4]),  "=r"((r)[5]),  "=r"((r)[6]),  "=r"((r)[7]), \
          "=r"((r)[8]),  "=r"((r)[9]),  "=r"((r)[10]), "=r"((r)[11]), \
          "=r"((r)[12]), "=r"((r)[13]), "=r"((r)[14]), "=r"((r)[15]), \
          "=r"((r)[16]), "=r"((r)[17]), "=r"((r)[18]), "=r"((r)[19]), \
          "=r"((r)[20]), "=r"((r)[21]), "=r"((r)[22]), "=r"((r)[23]), \
          "=r"((r)[24]), "=r"((r)[25]), "=r"((r)[26]), "=r"((r)[27]), \
          "=r"((r)[28]), "=r"((r)[29]), "=r"((r)[30]), "=r"((r)[31]) \
        : "r"(tmem_addr))

#if HAS_TCGEN05
static __device__ __forceinline__ void mma_bf16_ss(uint32_t d_tmem, uint64_t a_desc,
                                                   uint64_t b_desc, uint32_t enable) {
    asm volatile(
        "{\n\t"
        ".reg .pred p;\n\t"
        "setp.ne.u32 p, %5, 0;\n\t"
        "tcgen05.mma.cta_group::1.kind::f16 [%0], %1, %2, %3, {%4, %4, %4, %4}, p;\n\t"
        "}"
        :: "r"(d_tmem), "l"(a_desc), "l"(b_desc), "r"(MMA_IDESC), "r"(0u), "r"(enable)
        : "memory");
}
static __device__ __forceinline__ void bulk_g2s(uint32_t dst_smem, const void* src,
                                                uint32_t bytes, uint32_t mbar) {
    asm volatile(
        "cp.async.bulk.shared::cluster.global.mbarrier::complete_tx::bytes "
        "[%0], [%1], %2, [%3];"
        :: "r"(dst_smem), "l"(src), "r"(bytes), "r"(mbar) : "memory");
}
static __device__ __forceinline__ void cp_async16(uint32_t dst_smem, const void* src) {
    asm volatile("cp.async.cg.shared.global [%0], [%1], 16;"
                 :: "r"(dst_smem), "l"(src) : "memory");
}
#define CP_ASYNC_COMMIT() asm volatile("cp.async.commit_group;" ::: "memory")
#define CP_ASYNC_WAIT_1() asm volatile("cp.async.wait_group 1;" ::: "memory")
#define CP_ASYNC_WAIT_0() asm volatile("cp.async.wait_group 0;" ::: "memory")

static __device__ __forceinline__ void split2(float x0, float x1,
                                              uint32_t& hi01, uint32_t& lo01) {
    uint32_t h;
    asm("cvt.rn.bf16x2.f32 %0, %1, %2;" : "=r"(h) : "f"(x1), "f"(x0));
    float hf0 = __uint_as_float(h << 16);
    float hf1 = __uint_as_float(h & 0xFFFF0000u);
    float r0 = x0 - hf0;
    float r1 = x1 - hf1;
    uint32_t l;
    asm("cvt.rn.bf16x2.f32 %0, %1, %2;" : "=r"(l) : "f"(r1), "f"(r0));
    hi01 = h; lo01 = l;
}
#endif

static __device__ __forceinline__ int load_type(const void* ntype, long long r, int is64) {
    if (is64) return (int)((const long long*)ntype)[r];
    return ((const int*)ntype)[r];
}

// ============================================================================
// Kernel 1: detect node_type dtype (block 0) + split & pre-swizzle W.
// ============================================================================
__global__ void relemb_wsplit_kernel(const float* __restrict__ W,
                                     const unsigned int* __restrict__ t) {
    if (blockIdx.x == 0) {
        __shared__ int found;
        if (threadIdx.x == 0) found = 0;
        __syncthreads();
        for (int i = threadIdx.x; i < 4096; i += blockDim.x)
            if ((i & 1) && t[i] != 0u) found = 1;
        __syncthreads();
        if (threadIdx.x == 0) g_is64 = found ? 0 : 1;
    }
    int idx = blockIdx.x * 256 + threadIdx.x;
    float x = W[idx];
    __nv_bfloat16 hi = __float2bfloat16(x);
    __nv_bfloat16 lo = __float2bfloat16(x - __bfloat162float(hi));
    int j = idx >> 8;
    int k = idx & 255;
    int chunk = k >> 6, kk = k & 63;
    uint32_t byte = (uint32_t)chunk * 32768u + SW128((uint32_t)(j * 128 + kk * 2));
    *(__nv_bfloat16*)((char*)g_Whi + byte) = hi;
    *(__nv_bfloat16*)((char*)g_Wlo + byte) = lo;
}

// ============================================================================
// Kernel 2: per-256-row (tile pair) GEMM + select, 512 threads
// ============================================================================
__global__ __launch_bounds__(THREADS, 1) void relemb_gemm_kernel(
    const float* __restrict__ emb,
    const void*  __restrict__ ntype,
    const float* __restrict__ W,      // fp32 W (fallback path only)
    const float* __restrict__ bias,
    float* __restrict__ out,
    int nrows)
{
#if HAS_TCGEN05
    extern __shared__ char smem[];
    const uint32_t sb = smem_u32(smem);
    const int tid = threadIdx.x;
    const int wid = tid >> 5;
    const int lid = tid & 31;
    const long long cta_base = (long long)blockIdx.x * 256;   // 2 tiles of 128
    const int is64 = g_is64;

    // ---------------- prologue ----------------
    if (tid == 0) {
        #pragma unroll
        for (int s = 0; s < 8; s++) MBARRIER_INIT(sb + MB_COMMIT + s * 8, 1);
        #pragma unroll
        for (int c = 0; c < 4; c++) MBARRIER_INIT(sb + MB_WFULL + c * 8, 1);
    }
    if (wid == 0) TCGEN05_ALLOC(sb + SMEM_TMEM_PTR, 512);
    if (tid < 256) {
        ((float*)(smem + SMEM_BIAS))[tid] = bias[tid];
        long long rg = cta_base + tid;
        int ty = (rg < nrows) ? load_type(ntype, rg, is64) : 0;
        ((unsigned char*)(smem + SMEM_TMASK))[tid] = (unsigned char)ty;
    }

    // prefetch A for step 0 (chunk 0, tile 0) into staging buf 0
    {
        const uint32_t ab = sb + SMEM_A;
        #pragma unroll
        for (int i = 0; i < 2; ++i) {
            const int u = i * THREADS + tid;      // 0..1023 (32B segments)
            const int row = u >> 3, seg = u & 7;
            const long long rg = cta_base + row;
            if (rg < nrows) {
                const float* gp = emb + rg * D_DIM + seg * 8;
                const uint32_t dp = ab + (uint32_t)(row * 256 + seg * 32);
                cp_async16(dp, gp);
                cp_async16(dp + 16, gp + 4);
            }
        }
        CP_ASYNC_COMMIT();
    }
    __syncthreads();

    uint32_t tmem;
    asm volatile("ld.shared.b32 %0, [%1];" : "=r"(tmem) : "r"(sb + SMEM_TMEM_PTR));
    const unsigned char* tmask = (const unsigned char*)(smem + SMEM_TMASK);

    // ---------------- main loop: 8 steps = (chunk c = s>>1, tile t = s&1) ----
    #pragma unroll 1
    for (int s = 0; s < 8; s++) {
        const int c = s >> 1;
        const int t = s & 1;
        const long long tile_base = cta_base + (long long)t * TILE_M;

        // OUT buf (s&1) reuse: MMAs of step s-2 must be done.
        if (s >= 2) MBARRIER_WAIT_PARITY(sb + MB_COMMIT + (s - 2) * 8, 0);

        const uint32_t aBuf = SMEM_A + (uint32_t)(s & 1) * 32768u;  // fp32 staging
        const uint32_t oBuf = SMEM_O + (uint32_t)(s & 1) * 32768u;  // hi +0, lo +16384
        const uint32_t wHi  = SMEM_W;
        const uint32_t wLo  = wHi + 32768u;

        // --- W chunk via bulk DMA (single buffer), once per chunk, tid0.
        // Overwrite needs MMAs of chunk c-1 (step s-1) done: tid0-only wait;
        // commit(s-1) lands ~1536cyc into the step, ~when others hit the sync.
        if (t == 0 && tid == 0) {
            if (s >= 2) MBARRIER_WAIT_PARITY(sb + MB_COMMIT + (s - 1) * 8, 0);
            const uint32_t wfb = sb + MB_WFULL + c * 8;
            MBARRIER_EXPECT_TX(wfb, 65536u);
            bulk_g2s(sb + wHi, (const char*)g_Whi + c * 32768, 32768u, wfb);
            bulk_g2s(sb + wLo, (const char*)g_Wlo + c * 32768, 32768u, wfb);
        }

        // --- prefetch A for step s+1 into staging buf (s+1)&1 ---
        if (s < 7) {
            const int nc = (s + 1) >> 1, nt = (s + 1) & 1;
            const long long ntb = cta_base + (long long)nt * TILE_M;
            const uint32_t nb = sb + SMEM_A + (uint32_t)((s + 1) & 1) * 32768u;
            #pragma unroll
            for (int i = 0; i < 2; ++i) {
                const int u = i * THREADS + tid;
                const int row = u >> 3, seg = u & 7;
                const long long rg = ntb + row;
                if (rg < nrows) {
                    const float* gp = emb + rg * D_DIM + nc * 64 + seg * 8;
                    const uint32_t dp = nb + (uint32_t)(row * 256 + seg * 32);
                    cp_async16(dp, gp);
                    cp_async16(dp + 16, gp + 4);
                }
            }
            CP_ASYNC_COMMIT();
        }

        // --- wait for step s's A staging ---
        if (s < 7) { CP_ASYNC_WAIT_1(); } else { CP_ASYNC_WAIT_0(); }

        // --- single convert phase: LDS fp32 -> (entity: STG out) or
        //     (relation: split -> STS bf16 hi|lo swizzled) ---
        #pragma unroll
        for (int i = 0; i < 2; ++i) {
            const int u = i * THREADS + tid;
            const int row = u >> 3, seg = u & 7;
            const char* sp = smem + aBuf + (uint32_t)(row * 256 + seg * 32);
            const float4 a0 = *(const float4*)sp;
            const float4 a1 = *(const float4*)(sp + 16);
            const long long rg = tile_base + row;
            if (rg < nrows) {
                if (tmask[t * TILE_M + row] == 0) {
                    float4* dst = (float4*)(out + rg * D_DIM + c * 64 + seg * 8);
                    dst[0] = a0;
                    dst[1] = a1;
                } else {
                    uint32_t h0, h1, h2, h3, l0, l1, l2, l3;
                    split2(a0.x, a0.y, h0, l0);
                    split2(a0.z, a0.w, h1, l1);
                    split2(a1.x, a1.y, h2, l2);
                    split2(a1.z, a1.w, h3, l3);
                    const uint32_t sw = SW128((uint32_t)(row * 128 + seg * 16));
                    *(uint4*)(smem + oBuf + sw)          = make_uint4(h0, h1, h2, h3);
                    *(uint4*)(smem + oBuf + 16384u + sw) = make_uint4(l0, l1, l2, l3);
                }
            }
        }
        FENCE_PROXY_ASYNC_SHARED_CTA();
        __syncthreads();

        // --- 12 MMAs (hi*hi + hi*lo + lo*hi) into accumulator t, commit ---
        if (wid == 0) {
            if (elect_one()) {
                MBARRIER_WAIT_PARITY(sb + MB_WFULL + c * 8, 0);
                TCGEN05_FENCE_AFTER();
                const uint32_t dtm = tmem + (uint32_t)(t * 256);
                const uint64_t dAh = MAKE_SMEM_DESC(sb + oBuf);
                const uint64_t dAl = MAKE_SMEM_DESC(sb + oBuf + 16384u);
                const uint64_t dWh = MAKE_SMEM_DESC(sb + wHi);
                const uint64_t dWl = MAKE_SMEM_DESC(sb + wLo);
                uint32_t acc = (c != 0) ? 1u : 0u;
                #pragma unroll
                for (int m = 0; m < 4; m++) {
                    mma_bf16_ss(dtm, dAh + 2 * m, dWh + 2 * m, acc);
                    acc = 1u;
                }
                #pragma unroll
                for (int m = 0; m < 4; m++)
                    mma_bf16_ss(dtm, dAh + 2 * m, dWl + 2 * m, 1u);
                #pragma unroll
                for (int m = 0; m < 4; m++)
                    mma_bf16_ss(dtm, dAl + 2 * m, dWh + 2 * m, 1u);
                TCGEN05_COMMIT(sb + MB_COMMIT + s * 8);
            }
        }
    }

    // ------- epilogue: both tiles in parallel (warps 0-7: t0, 8-15: t1) ----
    {
        const float* sbias = (const float*)(smem + SMEM_BIAS);
        const int t = wid >> 3;                     // tile
        const int row = (wid & 3) * 32 + lid;
        const int cb0 = ((wid >> 2) & 1) * 128;     // col half
        MBARRIER_WAIT_PARITY(sb + MB_COMMIT + (6 + t) * 8, 0);
        TCGEN05_FENCE_AFTER();
        const uint32_t ptm = tmem + (uint32_t)(t * 256);
        const long long rg = cta_base + (long long)t * TILE_M + row;
        const bool rel = (rg < nrows) &&
            (((const unsigned char*)(smem + SMEM_TMASK))[t * TILE_M + row] == 1);
        #pragma unroll
        for (int pair = 0; pair < 2; pair++) {
            const int col0 = cb0 + pair * 64;
            uint32_t dreg[64];
            TCGEN05_LD_32X32B_X32(dreg,      ptm + (uint32_t)col0);
            TCGEN05_LD_32X32B_X32(dreg + 32, ptm + (uint32_t)(col0 + 32));
            TCGEN05_WAIT_LD();
            if (rel) {
                #pragma unroll
                for (int i = 0; i < 16; i++) {
                    const int col = col0 + 4 * i;
                    float4 v;
                    v.x = __uint_as_float(dreg[4 * i + 0]) + sbias[col + 0];
                    v.y = __uint_as_float(dreg[4 * i + 1]) + sbias[col + 1];
                    v.z = __uint_as_float(dreg[4 * i + 2]) + sbias[col + 2];
                    v.w = __uint_as_float(dreg[4 * i + 3]) + sbias[col + 3];
                    *(float4*)(out + rg * D_DIM + col) = v;
                }
            }
        }
    }

    __syncthreads();
    if (wid == 0) {
        TCGEN05_RELINQUISH();
        TCGEN05_DEALLOC(tmem, 512);
    }
#else
    // ======================= SIMT fallback (plain compute_103 pass) ========
    extern __shared__ char smem[];
    float* se = (float*)smem;                          // 128 x 256 f32 tile
    int* sm_mask = (int*)(smem + TILE_M * D_DIM * 4);  // 128 ints
    const int tid = threadIdx.x;
    const int is64 = g_is64;

    #pragma unroll 1
    for (int t = 0; t < 2; t++) {
        const long long tile_base = (long long)blockIdx.x * 256 + (long long)t * TILE_M;
        if (tile_base >= nrows) break;
        __syncthreads();
        if (tid < TILE_M) {
            long long rg = tile_base + tid;
            sm_mask[tid] = (rg < nrows) ? load_type(ntype, rg, is64) : 0;
        }
        for (int i = tid; i < TILE_M * D_DIM; i += THREADS) {
            int r = i >> 8;
            long long rg = tile_base + r;
            se[i] = (rg < nrows) ? emb[rg * D_DIM + (i & 255)] : 0.f;
        }
        __syncthreads();

        if (tid < 256) {
            const float bc = bias[tid];
            const float* wr = W + (long long)tid * D_DIM;
            for (int r = 0; r < TILE_M; r++) {
                long long rg = tile_base + r;
                if (rg >= nrows) break;
                if (sm_mask[r] == 1) {
                    const float* er = se + r * D_DIM;
                    float acc = 0.f;
                    #pragma unroll 8
                    for (int k = 0; k < D_DIM; k++) acc = fmaf(er[k], wr[k], acc);
                    out[rg * D_DIM + tid] = acc + bc;
                } else {
                    out[rg * D_DIM + tid] = se[r * D_DIM + tid];
                }
            }
        }
    }
#endif
}

// ============================================================================
// launch — same structure as the passing R7/R9/R10/R12 versions
// ============================================================================
extern "C" void kernel_launch(void* const* d_in, const int* in_sizes, int n_in,
                              void* d_out, int out_size) {
    const float* emb   = (const float*)d_in[0];
    const void*  ntype = d_in[1];
    const float* W     = (const float*)d_in[2];
    const float* b     = (const float*)d_in[3];
    float*       out   = (float*)d_out;
    const int nrows = in_sizes[1];

    relemb_wsplit_kernel<<<256, 256>>>(W, (const unsigned int*)ntype);

    cudaFuncSetAttribute(relemb_gemm_kernel,
                         cudaFuncAttributeMaxDynamicSharedMemorySize, SMEM_BYTES);
    const int ntiles = (nrows + TILE_M - 1) / TILE_M;
    const int npairs = (ntiles + 1) / 2;
    relemb_gemm_kernel<<<npairs, THREADS, SMEM_BYTES>>>(emb, ntype, W, b, out, nrows);
}